// round 16
// baseline (speedup 1.0000x reference)
#include <cuda_runtime.h>
#include <cuda_fp16.h>
#include <math.h>
#include <stdint.h>

// ---------------- problem constants ----------------
#define CB   64
#define CS   512
#define CD   768
#define CE   32
#define CL   16
#define CTQ  128
#define CH   3
#define CDK  128
#define CHDK 384
#define CQKV 1152
#define CDFF 3072
#define CNH  1024
#define CNL  3
#define NROWS (CB*CE*CL)     // 32768
#define NENT  (CB*CE)        // 2048
#define CEAP  896            // ent_proj padded N

// ---------------- device scratch ----------------
__device__ float   g_x  [NROWS*CD];
__device__ __half  g_xh [NROWS*CD];
__device__ __half  g_qkvh[NROWS*CQKV];
__device__ __half  g_oh [NROWS*CHDK];
__device__ __half  g_fh [NROWS*CDFF];
__device__ float   g_t  [NROWS*CD];

__device__ float   g_xc [NENT*CD];
__device__ __half  g_xch[NENT*CD];

__device__ __half  g_wqkvh[CNL*CQKV*CD];
__device__ __half  g_woh [CNL*CD*CHDK];
__device__ __half  g_wf1h[CNL*CDFF*CD];
__device__ __half  g_wf2h[CNL*CD*CDFF];
__device__ float   g_bqkv[CNL*CQKV];

__device__ __half  g_weah[CEAP*CD];
__device__ float   g_bea [CEAP];
__device__ __half  g_enth[NENT*CD];
__device__ __half  g_feath[CB*2*CD];
__device__ __half  g_w1h [CNH*2*CD];

__device__ float g_ent [NENT*CD];
__device__ float g_entp[NENT*CEAP];
__device__ float g_wa  [CB*CD];
__device__ float g_h   [CB*CNH];

// ---------------- helpers ----------------
__device__ __forceinline__ uint32_t smem_u32(const void* p) {
    uint32_t a;
    asm("{ .reg .u64 t; cvta.to.shared.u64 t, %1; cvt.u32.u64 %0, t; }" : "=r"(a) : "l"(p));
    return a;
}

__device__ __forceinline__ void ldmatrix_x4(uint32_t* r, uint32_t addr) {
    asm volatile("ldmatrix.sync.aligned.m8n8.x4.shared.b16 {%0,%1,%2,%3}, [%4];"
        : "=r"(r[0]), "=r"(r[1]), "=r"(r[2]), "=r"(r[3]) : "r"(addr));
}

__device__ __forceinline__ void mma16816(float* c, const uint32_t* a,
                                         uint32_t b0, uint32_t b1) {
    asm volatile("mma.sync.aligned.m16n8k16.row.col.f32.f16.f16.f32 "
        "{%0,%1,%2,%3}, {%4,%5,%6,%7}, {%8,%9}, {%0,%1,%2,%3};"
        : "+f"(c[0]), "+f"(c[1]), "+f"(c[2]), "+f"(c[3])
        : "r"(a[0]), "r"(a[1]), "r"(a[2]), "r"(a[3]), "r"(b0), "r"(b1));
}

// ---------------- tensor-core GEMM (mma.sync fp16, 1-term, K-chunk 64) ---
// C = Ah @ Wh^T + bias (+ Res).  W stored [N,K] K-major fp16.
// CTA tile 64x128, 128 threads (4 warps = 2m x 2n). 2-stage, 4 CTAs/SM.
#define ROWB    144
#define ATROWS  64
#define WTROWS  128
#define ATILE   (ATROWS*ROWB)
#define WTILE   (WTROWS*ROWB)
#define STAGE_BYTES (ATILE+WTILE)
#define STAGES  2
#define SMEM_DYN (STAGES*STAGE_BYTES + 128)

__global__ __launch_bounds__(128, 4) void gemm_mma(
    const __half* __restrict__ Ah,
    const __half* __restrict__ Wh,
    const float* __restrict__ bias,
    float* __restrict__ Cf,
    __half* __restrict__ Chi,
    int K, int AmS, int CmS,
    const float* __restrict__ Res, int ResS, int relu)
{
    extern __shared__ char dynsmem[];
    uint32_t sbase = (smem_u32(dynsmem) + 127u) & ~127u;

    int tid  = threadIdx.x;
    int wid  = tid >> 5, lane = tid & 31;
    int wm   = wid & 1, wn = wid >> 1;
    int m0   = blockIdx.y * 64, n0 = blockIdx.x * 128;

    const int NC = K >> 6;

    auto load_chunk = [&](int kc, int buf) {
        uint32_t tb = sbase + buf * STAGE_BYTES;
        #pragma unroll
        for (int i = 0; i < 12; i++) {
            int seg = tid + i * 128;
            uint32_t dst;
            const __half* src;
            if (seg < 512) {
                int row = seg >> 3, c = seg & 7;
                dst = tb + row * ROWB + c * 16;
                src = Ah + (size_t)(m0 + row) * AmS + kc * 64 + c * 8;
            } else {
                int s2 = seg - 512;
                int row = s2 >> 3, c = s2 & 7;
                dst = tb + ATILE + row * ROWB + c * 16;
                src = Wh + (size_t)(n0 + row) * K + kc * 64 + c * 8;
            }
            asm volatile("cp.async.cg.shared.global [%0], [%1], 16;" :: "r"(dst), "l"(src));
        }
        asm volatile("cp.async.commit_group;" ::: "memory");
    };

    float acc[2][8][4];
    #pragma unroll
    for (int i = 0; i < 2; i++)
        #pragma unroll
        for (int j = 0; j < 8; j++)
            #pragma unroll
            for (int q = 0; q < 4; q++) acc[i][j][q] = 0.f;

    load_chunk(0, 0);

    int lrow = lane & 15;
    int lcol = (lane >> 4) << 4;

    for (int c = 0; c < NC; c++) {
        asm volatile("cp.async.wait_group 0;" ::: "memory");
        __syncthreads();

        uint32_t sb = sbase + (c & 1) * STAGE_BYTES;

        if (c + 1 < NC) load_chunk(c + 1, (c + 1) & 1);

        uint32_t aAddr = sb + (uint32_t)(wm * 32 + lrow) * ROWB + lcol;
        uint32_t bAddr = sb + ATILE + (uint32_t)(wn * 64 + lrow) * ROWB + lcol;

        #pragma unroll
        for (int ks = 0; ks < 4; ks++) {
            uint32_t a[2][4], b[4][4];
            #pragma unroll
            for (int i = 0; i < 2; i++)
                ldmatrix_x4(a[i], aAddr + i * (16 * ROWB) + ks * 32);
            #pragma unroll
            for (int jj = 0; jj < 4; jj++)
                ldmatrix_x4(b[jj], bAddr + jj * (16 * ROWB) + ks * 32);
            #pragma unroll
            for (int i = 0; i < 2; i++)
                #pragma unroll
                for (int jj = 0; jj < 4; jj++) {
                    mma16816(acc[i][2 * jj],     a[i], b[jj][0], b[jj][2]);
                    mma16816(acc[i][2 * jj + 1], a[i], b[jj][1], b[jj][3]);
                }
        }
    }

    // ---------------- epilogue ----------------
    const float2* bp = (const float2*)(bias + n0 + wn * 64);
    float2 bv[8];
    #pragma unroll
    for (int j = 0; j < 8; j++) bv[j] = bp[j * 4 + (lane & 3)];

    #pragma unroll
    for (int i = 0; i < 2; i++) {
        int m_lo = m0 + wm * 32 + i * 16 + (lane >> 2);
        #pragma unroll
        for (int j = 0; j < 8; j++) {
            int n = n0 + wn * 64 + j * 8 + (lane & 3) * 2;
            float v0 = acc[i][j][0] + bv[j].x;
            float v1 = acc[i][j][1] + bv[j].y;
            float v2 = acc[i][j][2] + bv[j].x;
            float v3 = acc[i][j][3] + bv[j].y;
            if (relu) {
                v0 = fmaxf(v0, 0.f); v1 = fmaxf(v1, 0.f);
                v2 = fmaxf(v2, 0.f); v3 = fmaxf(v3, 0.f);
            }
            if (Res) {
                float2 r0 = *(const float2*)(Res + (size_t)m_lo * ResS + n);
                float2 r1 = *(const float2*)(Res + (size_t)(m_lo + 8) * ResS + n);
                v0 += r0.x; v1 += r0.y; v2 += r1.x; v3 += r1.y;
            }
            if (Cf) {
                *(float2*)(Cf + (size_t)m_lo * CmS + n)        = make_float2(v0, v1);
                *(float2*)(Cf + (size_t)(m_lo + 8) * CmS + n)  = make_float2(v2, v3);
            }
            if (Chi) {
                __half2 ph = __halves2half2(__float2half_rn(v0), __float2half_rn(v1));
                *(uint32_t*)(Chi + (size_t)m_lo * CmS + n) = *(uint32_t*)&ph;
                ph = __halves2half2(__float2half_rn(v2), __float2half_rn(v3));
                *(uint32_t*)(Chi + (size_t)(m_lo + 8) * CmS + n) = *(uint32_t*)&ph;
            }
        }
    }
}

// ---------------- weight transpose + fp16 convert (layer-batched) --------
__global__ void wconvL_kernel(const float* __restrict__ src,
                              __half* __restrict__ dh,
                              int K, int N, int dstLd,
                              size_t srcLS, size_t dstLS) {
    __shared__ float ts[32][33];
    int L = blockIdx.z;
    src += L * srcLS; dh += L * dstLS;
    int n0 = blockIdx.x * 32, k0 = blockIdx.y * 32;
    int tx = threadIdx.x, ty = threadIdx.y;
    #pragma unroll
    for (int j = 0; j < 4; j++)
        ts[ty + 8 * j][tx] = src[(size_t)(k0 + ty + 8 * j) * N + n0 + tx];
    __syncthreads();
    #pragma unroll
    for (int j = 0; j < 4; j++) {
        float v = ts[tx][ty + 8 * j];
        size_t di = (size_t)(n0 + ty + 8 * j) * dstLd + k0 + tx;
        dh[di] = __float2half_rn(v);
    }
}

// all QKV conversions in one launch: z = layer*3 + mat
__global__ void wconv3_kernel(const float* __restrict__ srcQ,
                              const float* __restrict__ srcK,
                              const float* __restrict__ srcV,
                              __half* __restrict__ dh) {
    __shared__ float ts[32][33];
    int z = blockIdx.z;
    int L = z / 3, mat = z % 3;
    const float* src = (mat == 0) ? srcQ : (mat == 1) ? srcK : srcV;
    src += (size_t)L * CD * CHDK;
    dh  += (size_t)L * CQKV * CD;
    int rowOff = mat * CHDK;
    int n0 = blockIdx.x * 32, k0 = blockIdx.y * 32;
    int tx = threadIdx.x, ty = threadIdx.y;
    #pragma unroll
    for (int j = 0; j < 4; j++)
        ts[ty + 8 * j][tx] = src[(size_t)(k0 + ty + 8 * j) * CHDK + n0 + tx];
    __syncthreads();
    #pragma unroll
    for (int j = 0; j < 4; j++) {
        float v = ts[tx][ty + 8 * j];
        size_t di = (size_t)(rowOff + n0 + ty + 8 * j) * CD + k0 + tx;
        dh[di] = __float2half_rn(v);
    }
}

__global__ void wconv_ea_kernel(const float* __restrict__ src) {
    __shared__ float ts[32][33];
    int n0 = blockIdx.x * 32, k0 = blockIdx.y * 32;
    int tx = threadIdx.x, ty = threadIdx.y;
    #pragma unroll
    for (int j = 0; j < 4; j++) {
        int n = n0 + tx;
        ts[ty + 8 * j][tx] = (n < 770) ? src[(size_t)(k0 + ty + 8 * j) * 770 + n] : 0.f;
    }
    __syncthreads();
    #pragma unroll
    for (int j = 0; j < 4; j++) {
        int n = n0 + ty + 8 * j;
        if (n < 770)
            g_weah[(size_t)n * CD + k0 + tx] = __float2half_rn(ts[tx][ty + 8 * j]);
    }
}

__global__ void bqkv_kernel(const float* __restrict__ bq,
                            const float* __restrict__ bk,
                            const float* __restrict__ bv,
                            const float* __restrict__ b_ea) {
    int i = blockIdx.x;
    for (int j = threadIdx.x; j < CQKV; j += 256)
        g_bqkv[i * CQKV + j] =
            (j < CHDK) ? bq[i * CHDK + j] :
            (j < 2 * CHDK) ? bk[i * CHDK + j - CHDK] : bv[i * CHDK + j - 2 * CHDK];
    if (i == 0)
        for (int j = threadIdx.x; j < CEAP; j += 256)
            g_bea[j] = (j < 770) ? b_ea[j] : 0.f;
}

// ---------------- gather spans into g_x (+ fp16) ----------------
__global__ void gather_kernel(const float* __restrict__ q_enc,
                              const int* __restrict__ ranges) {
    int row = blockIdx.x;
    int be = row >> 4, l = row & 15;
    int b = be >> 5, e = be & 31;
    int st = ranges[(b * CE + e) * 2];
    int en = ranges[(b * CE + e) * 2 + 1];
    int src = min(max(st + l, 0), CS - 1);
    bool m = l < (en - st);
    const float* s = q_enc + ((size_t)b * CS + src) * CD;
    size_t base = (size_t)row * CD;
    for (int i = threadIdx.x; i < CD; i += 256) {
        float v = m ? s[i] : 0.f;
        g_x[base + i] = v;
        g_xh[base + i] = __float2half_rn(v);
    }
}

// ---------------- per-(span,head) attention ----------------
__global__ void attn_kernel() {
    int nh = blockIdx.x;
    int n = nh / CH, h = nh % CH;
    __shared__ float qs[16][129], ks[16][129], vs[16][129];
    __shared__ float sc[16][17];
    int tid = threadIdx.x;
    for (int idx = tid; idx < 16 * 128; idx += 128) {
        int l = idx >> 7, d = idx & 127;
        size_t base = ((size_t)(n * CL + l)) * CQKV + h * CDK + d;
        qs[l][d] = __half2float(g_qkvh[base]);
        ks[l][d] = __half2float(g_qkvh[base + CHDK]);
        vs[l][d] = __half2float(g_qkvh[base + 2 * CHDK]);
    }
    __syncthreads();
    const float scale = 0.088388347648318447f;
    for (int p = tid; p < 256; p += 128) {
        int qi = p >> 4, ki = p & 15;
        float s = 0.f;
        #pragma unroll
        for (int d = 0; d < 128; d++) s += qs[qi][d] * ks[ki][d];
        sc[qi][ki] = s * scale;
    }
    __syncthreads();
    if (tid < 16) {
        float m = -1e30f;
        #pragma unroll
        for (int k = 0; k < 16; k++) m = fmaxf(m, sc[tid][k]);
        float sum = 0.f;
        #pragma unroll
        for (int k = 0; k < 16; k++) { float e = __expf(sc[tid][k] - m); sc[tid][k] = e; sum += e; }
        float inv = 1.f / sum;
        #pragma unroll
        for (int k = 0; k < 16; k++) sc[tid][k] *= inv;
    }
    __syncthreads();
    int d = tid;
    #pragma unroll
    for (int qi = 0; qi < 16; qi++) {
        float acc = 0.f;
        #pragma unroll
        for (int k = 0; k < 16; k++) acc += sc[qi][k] * vs[k][d];
        g_oh[((size_t)(n * CL + qi)) * CHDK + h * CDK + d] = __float2half_rn(acc);
    }
}

__global__ void attn0_kernel() {
    int nh = blockIdx.x;
    int n = nh / CH, h = nh % CH;
    __shared__ float ks[16][129], vs[16][129];
    __shared__ float q0[128];
    __shared__ float p[16];
    int tid = threadIdx.x;
    for (int idx = tid; idx < 16 * 128; idx += 128) {
        int l = idx >> 7, d = idx & 127;
        size_t base = ((size_t)(n * CL + l)) * CQKV + h * CDK + d;
        ks[l][d] = __half2float(g_qkvh[base + CHDK]);
        vs[l][d] = __half2float(g_qkvh[base + 2 * CHDK]);
    }
    q0[tid] = __half2float(g_qkvh[((size_t)(n * CL)) * CQKV + h * CDK + tid]);
    __syncthreads();
    const float scale = 0.088388347648318447f;
    if (tid < 16) {
        float s = 0.f;
        #pragma unroll
        for (int d = 0; d < 128; d++) s += q0[d] * ks[tid][d];
        p[tid] = s * scale;
    }
    __syncthreads();
    if (tid == 0) {
        float m = -1e30f;
        #pragma unroll
        for (int k = 0; k < 16; k++) m = fmaxf(m, p[k]);
        float sum = 0.f;
        #pragma unroll
        for (int k = 0; k < 16; k++) { float e = __expf(p[k] - m); p[k] = e; sum += e; }
        float inv = 1.f / sum;
        #pragma unroll
        for (int k = 0; k < 16; k++) p[k] *= inv;
    }
    __syncthreads();
    float acc = 0.f;
    #pragma unroll
    for (int k = 0; k < 16; k++) acc += p[k] * vs[k][tid];
    g_oh[(size_t)n * CHDK + h * CDK + tid] = __float2half_rn(acc);
}

// ---------------- LayerNorm kernels (residual pre-folded into g_t) -------
__device__ __forceinline__ float blockReduceSum(float val) {
    __shared__ float sh[32];
    int lane = threadIdx.x & 31, wid = threadIdx.x >> 5;
    #pragma unroll
    for (int o = 16; o > 0; o >>= 1) val += __shfl_xor_sync(0xffffffffu, val, o);
    if (lane == 0) sh[wid] = val;
    __syncthreads();
    int nw = (blockDim.x + 31) >> 5;
    val = (threadIdx.x < nw) ? sh[lane] : 0.f;
    if (wid == 0) {
        #pragma unroll
        for (int o = 16; o > 0; o >>= 1) val += __shfl_xor_sync(0xffffffffu, val, o);
    }
    return val;
}

__global__ void add_ln_kernel(const float* __restrict__ gamma,
                              const float* __restrict__ beta) {
    int row = blockIdx.x;
    int tid = threadIdx.x;
    float v[3];
    float s = 0.f;
    #pragma unroll
    for (int j = 0; j < 3; j++) {
        v[j] = g_t[(size_t)row * CD + tid + j * 256];
        s += v[j];
    }
    s = blockReduceSum(s);
    __shared__ float mean_s, rstd_s;
    if (tid == 0) mean_s = s * (1.f / CD);
    __syncthreads();
    float m = mean_s;
    float vv = 0.f;
    #pragma unroll
    for (int j = 0; j < 3; j++) { float d = v[j] - m; vv += d * d; }
    vv = blockReduceSum(vv);
    if (tid == 0) rstd_s = rsqrtf(vv * (1.f / CD) + 1e-5f);
    __syncthreads();
    float r = rstd_s;
    #pragma unroll
    for (int j = 0; j < 3; j++) {
        int c = tid + j * 256;
        float o = (v[j] - m) * r * gamma[c] + beta[c];
        size_t idx = (size_t)row * CD + c;
        g_x[idx] = o;
        g_xh[idx] = __float2half_rn(o);
    }
}

__global__ void ln1_last_kernel(const float* __restrict__ gamma,
                                const float* __restrict__ beta) {
    int r = blockIdx.x;
    int tid = threadIdx.x;
    float v[3];
    float s = 0.f;
    #pragma unroll
    for (int j = 0; j < 3; j++) {
        v[j] = g_t[(size_t)r * CD + tid + j * 256];
        s += v[j];
    }
    s = blockReduceSum(s);
    __shared__ float mean_s, rstd_s;
    if (tid == 0) mean_s = s * (1.f / CD);
    __syncthreads();
    float m = mean_s;
    float vv = 0.f;
    #pragma unroll
    for (int j = 0; j < 3; j++) { float d = v[j] - m; vv += d * d; }
    vv = blockReduceSum(vv);
    if (tid == 0) rstd_s = rsqrtf(vv * (1.f / CD) + 1e-5f);
    __syncthreads();
    float rr = rstd_s;
    #pragma unroll
    for (int j = 0; j < 3; j++) {
        int c = tid + j * 256;
        float o = (v[j] - m) * rr * gamma[c] + beta[c];
        size_t idx = (size_t)r * CD + c;
        g_xc[idx] = o;
        g_xch[idx] = __float2half_rn(o);
    }
}

__global__ void ln2_last_kernel(const float* __restrict__ gamma,
                                const float* __restrict__ beta) {
    int r = blockIdx.x;
    int tid = threadIdx.x;
    float v[3];
    float s = 0.f;
    #pragma unroll
    for (int j = 0; j < 3; j++) {
        v[j] = g_t[(size_t)r * CD + tid + j * 256];
        s += v[j];
    }
    s = blockReduceSum(s);
    __shared__ float mean_s, rstd_s;
    if (tid == 0) mean_s = s * (1.f / CD);
    __syncthreads();
    float m = mean_s;
    float vv = 0.f;
    #pragma unroll
    for (int j = 0; j < 3; j++) { float d = v[j] - m; vv += d * d; }
    vv = blockReduceSum(vv);
    if (tid == 0) rstd_s = rsqrtf(vv * (1.f / CD) + 1e-5f);
    __syncthreads();
    float rr = rstd_s;
    #pragma unroll
    for (int j = 0; j < 3; j++) {
        int c = tid + j * 256;
        float o = (v[j] - m) * rr * gamma[c] + beta[c];
        size_t idx = (size_t)r * CD + c;
        g_ent[idx] = o;
        g_enth[idx] = __float2half_rn(o);
    }
}

// ---------------- fused pooling: attention weights + masked sum + wa -----
// one block per batch b; ent_proj[b] cached in smem; skips t >= qlen.
#define PSMEM ((32*770 + 772 + 32) * 4)
__global__ void pool_fused_kernel(const float* __restrict__ q_enc,
                                  const float* __restrict__ hint,
                                  const int* __restrict__ qlen) {
    int b = blockIdx.x;
    extern __shared__ float sm[];
    float* ep = sm;               // 32*770
    float* qv = sm + 32 * 770;    // 770 (+pad)
    float* A  = qv + 772;         // 32
    __shared__ float lg[32];
    int tid = threadIdx.x;        // 256

    for (int i = tid; i < 32 * 770; i += 256) {
        int e = i / 770, d = i - e * 770;
        ep[i] = g_entp[((size_t)b * CE + e) * CEAP + d];
    }
    if (tid < 32) A[tid] = 0.f;
    __syncthreads();

    int n = qlen[b];
    int e = tid >> 3, sub = tid & 7;
    for (int t = 0; t < n; t++) {
        for (int i = tid; i < 770; i += 256)
            qv[i] = (i < CD) ? q_enc[((size_t)b * CS + t) * CD + i]
                             : hint[((size_t)b * CTQ + t) * 2 + (i - CD)];
        __syncthreads();
        float p = 0.f;
        for (int d = sub; d < 770; d += 8) p += qv[d] * ep[e * 770 + d];
        p += __shfl_down_sync(0xffffffffu, p, 4, 8);
        p += __shfl_down_sync(0xffffffffu, p, 2, 8);
        p += __shfl_down_sync(0xffffffffu, p, 1, 8);
        if (sub == 0) lg[e] = p;
        __syncthreads();
        if (tid < 32) {
            float v = lg[tid];
            float m = v;
            #pragma unroll
            for (int o = 16; o > 0; o >>= 1) m = fmaxf(m, __shfl_xor_sync(0xffffffffu, m, o));
            float ex = __expf(v - m);
            float smv = ex;
            #pragma unroll
            for (int o = 16; o > 0; o >>= 1) smv += __shfl_xor_sync(0xffffffffu, smv, o);
            A[tid] += ex / smv;
        }
        __syncthreads();
    }

    #pragma unroll
    for (int j = 0; j < 3; j++) {
        int d = tid + j * 256;
        float s = 0.f;
        #pragma unroll
        for (int e2 = 0; e2 < 32; e2++) s += A[e2] * g_ent[((size_t)b * CE + e2) * CD + d];
        g_wa[(size_t)b * CD + d] = s;
    }
}

// feat (fp16) = [q_enc[b,0,:], wa[b,:]]
__global__ void feat_kernel(const float* __restrict__ q_enc) {
    int b = blockIdx.x;
    for (int i = threadIdx.x; i < 2 * CD; i += 256)
        g_feath[(size_t)b * 2 * CD + i] = __float2half_rn(
            (i < CD) ? q_enc[(size_t)b * CS * CD + i] : g_wa[(size_t)b * CD + (i - CD)]);
}

__global__ void head_out_kernel(const float* __restrict__ W2,
                                const float* __restrict__ b2,
                                float* __restrict__ out) {
    int b = blockIdx.x, tid = threadIdx.x;
    float s = 0.f;
    for (int n = tid; n < CNH; n += 256) s += g_h[(size_t)b * CNH + n] * W2[n];
    s = blockReduceSum(s);
    if (tid == 0) out[b] = s + b2[0];
}

// ---------------- host ----------------
template <typename T>
static T* dsym(const void* symbol) {
    void* p = nullptr;
    cudaGetSymbolAddress(&p, symbol);
    return (T*)p;
}

extern "C" void kernel_launch(void* const* d_in, const int* in_sizes, int n_in,
                              void* d_out, int out_size) {
    const float* q_enc  = (const float*)d_in[0];
    const int*   q_qlen = (const int*)  d_in[1];
    const float* hint   = (const float*)d_in[2];
    const int*   ranges = (const int*)  d_in[3];
    const float* Wq  = (const float*)d_in[4];
    const float* bq  = (const float*)d_in[5];
    const float* Wk  = (const float*)d_in[6];
    const float* bk  = (const float*)d_in[7];
    const float* Wv  = (const float*)d_in[8];
    const float* bv  = (const float*)d_in[9];
    const float* Wo  = (const float*)d_in[10];
    const float* bo  = (const float*)d_in[11];
    const float* ln1g = (const float*)d_in[12];
    const float* ln1b = (const float*)d_in[13];
    const float* Wf1 = (const float*)d_in[14];
    const float* bf1 = (const float*)d_in[15];
    const float* Wf2 = (const float*)d_in[16];
    const float* bf2 = (const float*)d_in[17];
    const float* ln2g = (const float*)d_in[18];
    const float* ln2b = (const float*)d_in[19];
    const float* W_ea = (const float*)d_in[20];
    const float* b_ea = (const float*)d_in[21];
    const float* W1  = (const float*)d_in[22];
    const float* b1  = (const float*)d_in[23];
    const float* W2  = (const float*)d_in[24];
    const float* b2  = (const float*)d_in[25];
    float* out = (float*)d_out;

    cudaFuncSetAttribute(gemm_mma, cudaFuncAttributeMaxDynamicSharedMemorySize, SMEM_DYN);
    cudaFuncSetAttribute(pool_fused_kernel, cudaFuncAttributeMaxDynamicSharedMemorySize, PSMEM);

    __half* xh  = dsym<__half>(g_xh);
    __half* oh  = dsym<__half>(g_oh);
    __half* fh  = dsym<__half>(g_fh);
    __half* xch = dsym<__half>(g_xch);
    __half* qkvh = dsym<__half>(g_qkvh);
    float* x_  = dsym<float>(g_x);
    float* xc_ = dsym<float>(g_xc);
    float* t_  = dsym<float>(g_t);
    __half* wqkvh = dsym<__half>(g_wqkvh);
    __half* woh   = dsym<__half>(g_woh);
    __half* wf1h  = dsym<__half>(g_wf1h);
    __half* wf2h  = dsym<__half>(g_wf2h);
    __half* weah  = dsym<__half>(g_weah);
    __half* enth  = dsym<__half>(g_enth);
    __half* feath = dsym<__half>(g_feath);
    __half* w1h   = dsym<__half>(g_w1h);
    float* bqkv = dsym<float>(g_bqkv);
    float* bea  = dsym<float>(g_bea);
    float* entp = dsym<float>(g_entp);
    float* h_   = dsym<float>(g_h);

    dim3 wblk(32, 8);

    // all QKV weight conversions (3 layers x 3 mats), bias concat, gather
    wconv3_kernel<<<dim3(CHDK/32, CD/32, 3*CNL), wblk>>>(Wq, Wk, Wv, wqkvh);
    bqkv_kernel<<<CNL, 256>>>(bq, bk, bv, b_ea);
    gather_kernel<<<NROWS, 256>>>(q_enc, ranges);

    // layer-0 QKV GEMM
    gemm_mma<<<dim3(CQKV/128, NROWS/64), 128, SMEM_DYN>>>(
        xh, wqkvh, bqkv, nullptr, qkvh, CD, CD, CQKV, nullptr, 0, 0);

    // remaining weight conversions (layer-batched)
    wconvL_kernel<<<dim3(CD/32, CHDK/32, CNL), wblk>>>(
        Wo, woh, CHDK, CD, CHDK, (size_t)CHDK*CD, (size_t)CD*CHDK);
    wconvL_kernel<<<dim3(CDFF/32, CD/32, CNL), wblk>>>(
        Wf1, wf1h, CD, CDFF, CD, (size_t)CD*CDFF, (size_t)CDFF*CD);
    wconvL_kernel<<<dim3(CD/32, CDFF/32, CNL), wblk>>>(
        Wf2, wf2h, CDFF, CD, CDFF, (size_t)CDFF*CD, (size_t)CD*CDFF);
    wconv_ea_kernel<<<dim3((770 + 31)/32, CD/32), wblk>>>(W_ea);
    wconvL_kernel<<<dim3(CNH/32, (2*CD)/32, 1), wblk>>>(
        W1, w1h, 2*CD, CNH, 2*CD, 0, 0);

    // ---- layers 0 .. NL-2: full-width pipeline ----
    for (int i = 0; i < CNL - 1; i++) {
        size_t oQ  = (size_t)i * CQKV * CD;
        size_t oO  = (size_t)i * CD * CHDK;
        size_t oF1 = (size_t)i * CDFF * CD;
        size_t oF2 = (size_t)i * CD * CDFF;

        if (i > 0) {
            gemm_mma<<<dim3(CQKV/128, NROWS/64), 128, SMEM_DYN>>>(
                xh, wqkvh + oQ, bqkv + i*CQKV, nullptr, qkvh, CD, CD, CQKV, nullptr, 0, 0);
        }

        attn_kernel<<<NENT * CH, 128>>>();

        // Wo with residual fold (t_ = out + bias + x)
        gemm_mma<<<dim3(CD/128, NROWS/64), 128, SMEM_DYN>>>(
            oh, woh + oO, bo + i*CD, t_, nullptr, CHDK, CHDK, CD, x_, CD, 0);

        add_ln_kernel<<<NROWS, 256>>>(ln1g + i*CD, ln1b + i*CD);

        gemm_mma<<<dim3(CDFF/128, NROWS/64), 128, SMEM_DYN>>>(
            xh, wf1h + oF1, bf1 + i*CDFF, nullptr, fh, CD, CD, CDFF, nullptr, 0, 1);

        // FFN2 with residual fold
        gemm_mma<<<dim3(CD/128, NROWS/64), 128, SMEM_DYN>>>(
            fh, wf2h + oF2, bf2 + i*CD, t_, nullptr, CDFF, CDFF, CD, x_, CD, 0);

        add_ln_kernel<<<NROWS, 256>>>(ln2g + i*CD, ln2b + i*CD);
    }

    // ---- layer NL-1 (last): only span-row 0 needed post-attention ----
    {
        const int i = CNL - 1;
        size_t oQ  = (size_t)i * CQKV * CD;
        size_t oO  = (size_t)i * CD * CHDK;
        size_t oF1 = (size_t)i * CDFF * CD;
        size_t oF2 = (size_t)i * CD * CDFF;

        gemm_mma<<<dim3((2*CHDK)/128, NROWS/64), 128, SMEM_DYN>>>(
            xh, wqkvh + oQ + (size_t)CHDK*CD, bqkv + i*CQKV + CHDK,
            nullptr, qkvh + CHDK, CD, CD, CQKV, nullptr, 0, 0);

        gemm_mma<<<dim3(CHDK/128, NENT/64), 128, SMEM_DYN>>>(
            xh, wqkvh + oQ, bqkv + i*CQKV,
            nullptr, qkvh, CD, CL*CD, CL*CQKV, nullptr, 0, 0);

        attn0_kernel<<<NENT * CH, 128>>>();

        // compact Wo: residual = g_x rows r*16 (stride CL*CD)
        gemm_mma<<<dim3(CD/128, NENT/64), 128, SMEM_DYN>>>(
            oh, woh + oO, bo + i*CD, t_, nullptr, CHDK, CHDK, CD, x_, CL*CD, 0);

        ln1_last_kernel<<<NENT, 256>>>(ln1g + i*CD, ln1b + i*CD);

        gemm_mma<<<dim3(CDFF/128, NENT/64), 128, SMEM_DYN>>>(
            xch, wf1h + oF1, bf1 + i*CDFF, nullptr, fh, CD, CD, CDFF, nullptr, 0, 1);

        // compact FFN2: residual = g_xc (stride CD)
        gemm_mma<<<dim3(CD/128, NENT/64), 128, SMEM_DYN>>>(
            fh, wf2h + oF2, bf2 + i*CD, t_, nullptr, CDFF, CDFF, CD, xc_, CD, 0);

        ln2_last_kernel<<<NENT, 256>>>(ln2g + i*CD, ln2b + i*CD);
    }

    // ---- tail: ent_proj + fused pooling + head ----
    gemm_mma<<<dim3(CEAP/128, NENT/64), 128, SMEM_DYN>>>(
        enth, weah, bea, entp, nullptr, CD, CD, CEAP, nullptr, 0, 0);

    pool_fused_kernel<<<CB, 256, PSMEM>>>(q_enc, hint, q_qlen);
    feat_kernel<<<CB, 256>>>(q_enc);

    gemm_mma<<<dim3(CNH/128, CB/64), 128, SMEM_DYN>>>(
        feath, w1h, b1, h_, nullptr, 2*CD, 2*CD, CNH, nullptr, 0, 1);

    head_out_kernel<<<CB, 256>>>(W2, b2, out);
}

// round 17
// speedup vs baseline: 1.1192x; 1.1192x over previous
#include <cuda_runtime.h>
#include <cuda_fp16.h>
#include <math.h>
#include <stdint.h>

// ---------------- problem constants ----------------
#define CB   64
#define CS   512
#define CD   768
#define CE   32
#define CL   16
#define CTQ  128
#define CH   3
#define CDK  128
#define CHDK 384
#define CQKV 1152
#define CDFF 3072
#define CNH  1024
#define CNL  3
#define NROWS (CB*CE*CL)     // 32768
#define NENT  (CB*CE)        // 2048
#define CEAP  896            // ent_proj padded N

// ---------------- device scratch ----------------
__device__ float   g_x  [NROWS*CD];
__device__ __half  g_xh [NROWS*CD];
__device__ __half  g_qkvh[NROWS*CQKV];
__device__ __half  g_oh [NROWS*CHDK];
__device__ __half  g_fh [NROWS*CDFF];
__device__ float   g_t  [NROWS*CD];

__device__ float   g_xc [NENT*CD];
__device__ __half  g_xch[NENT*CD];

__device__ __half  g_wqkvh[CNL*CQKV*CD];
__device__ __half  g_woh [CNL*CD*CHDK];
__device__ __half  g_wf1h[CNL*CDFF*CD];
__device__ __half  g_wf2h[CNL*CD*CDFF];
__device__ float   g_bqkv[CNL*CQKV];

__device__ __half  g_weah[CEAP*CD];
__device__ float   g_bea [CEAP];
__device__ __half  g_enth[NENT*CD];
__device__ __half  g_feath[CB*2*CD];
__device__ __half  g_w1h [CNH*2*CD];

__device__ float g_ent [NENT*CD];
__device__ float g_entp[NENT*CEAP];
__device__ float g_attnw[CB*CTQ*CE];
__device__ float g_wa  [CB*CD];
__device__ float g_h   [CB*CNH];

// ---------------- helpers ----------------
__device__ __forceinline__ uint32_t smem_u32(const void* p) {
    uint32_t a;
    asm("{ .reg .u64 t; cvta.to.shared.u64 t, %1; cvt.u32.u64 %0, t; }" : "=r"(a) : "l"(p));
    return a;
}

__device__ __forceinline__ void ldmatrix_x4(uint32_t* r, uint32_t addr) {
    asm volatile("ldmatrix.sync.aligned.m8n8.x4.shared.b16 {%0,%1,%2,%3}, [%4];"
        : "=r"(r[0]), "=r"(r[1]), "=r"(r[2]), "=r"(r[3]) : "r"(addr));
}

__device__ __forceinline__ void mma16816(float* c, const uint32_t* a,
                                         uint32_t b0, uint32_t b1) {
    asm volatile("mma.sync.aligned.m16n8k16.row.col.f32.f16.f16.f32 "
        "{%0,%1,%2,%3}, {%4,%5,%6,%7}, {%8,%9}, {%0,%1,%2,%3};"
        : "+f"(c[0]), "+f"(c[1]), "+f"(c[2]), "+f"(c[3])
        : "r"(a[0]), "r"(a[1]), "r"(a[2]), "r"(a[3]), "r"(b0), "r"(b1));
}

// ---------------- tensor-core GEMM (mma.sync fp16, 1-term, K-chunk 64) ---
// C = Ah @ Wh^T + bias.  W stored [N,K] K-major fp16.
// CTA tile 64x128, 128 threads (4 warps = 2m x 2n). 2-stage, 4 CTAs/SM.
#define ROWB    144
#define ATROWS  64
#define WTROWS  128
#define ATILE   (ATROWS*ROWB)
#define WTILE   (WTROWS*ROWB)
#define STAGE_BYTES (ATILE+WTILE)
#define STAGES  2
#define SMEM_DYN (STAGES*STAGE_BYTES + 128)

__global__ __launch_bounds__(128, 4) void gemm_mma(
    const __half* __restrict__ Ah,
    const __half* __restrict__ Wh,
    const float* __restrict__ bias,
    float* __restrict__ Cf,
    __half* __restrict__ Chi,
    int K, int AmS, int CmS, int relu)
{
    extern __shared__ char dynsmem[];
    uint32_t sbase = (smem_u32(dynsmem) + 127u) & ~127u;

    int tid  = threadIdx.x;
    int wid  = tid >> 5, lane = tid & 31;
    int wm   = wid & 1, wn = wid >> 1;
    int m0   = blockIdx.y * 64, n0 = blockIdx.x * 128;

    const int NC = K >> 6;

    auto load_chunk = [&](int kc, int buf) {
        uint32_t tb = sbase + buf * STAGE_BYTES;
        #pragma unroll
        for (int i = 0; i < 12; i++) {
            int seg = tid + i * 128;
            uint32_t dst;
            const __half* src;
            if (seg < 512) {
                int row = seg >> 3, c = seg & 7;
                dst = tb + row * ROWB + c * 16;
                src = Ah + (size_t)(m0 + row) * AmS + kc * 64 + c * 8;
            } else {
                int s2 = seg - 512;
                int row = s2 >> 3, c = s2 & 7;
                dst = tb + ATILE + row * ROWB + c * 16;
                src = Wh + (size_t)(n0 + row) * K + kc * 64 + c * 8;
            }
            asm volatile("cp.async.cg.shared.global [%0], [%1], 16;" :: "r"(dst), "l"(src));
        }
        asm volatile("cp.async.commit_group;" ::: "memory");
    };

    float acc[2][8][4];
    #pragma unroll
    for (int i = 0; i < 2; i++)
        #pragma unroll
        for (int j = 0; j < 8; j++)
            #pragma unroll
            for (int q = 0; q < 4; q++) acc[i][j][q] = 0.f;

    load_chunk(0, 0);

    int lrow = lane & 15;
    int lcol = (lane >> 4) << 4;

    for (int c = 0; c < NC; c++) {
        asm volatile("cp.async.wait_group 0;" ::: "memory");
        __syncthreads();

        uint32_t sb = sbase + (c & 1) * STAGE_BYTES;

        if (c + 1 < NC) load_chunk(c + 1, (c + 1) & 1);

        uint32_t aAddr = sb + (uint32_t)(wm * 32 + lrow) * ROWB + lcol;
        uint32_t bAddr = sb + ATILE + (uint32_t)(wn * 64 + lrow) * ROWB + lcol;

        #pragma unroll
        for (int ks = 0; ks < 4; ks++) {
            uint32_t a[2][4], b[4][4];
            #pragma unroll
            for (int i = 0; i < 2; i++)
                ldmatrix_x4(a[i], aAddr + i * (16 * ROWB) + ks * 32);
            #pragma unroll
            for (int jj = 0; jj < 4; jj++)
                ldmatrix_x4(b[jj], bAddr + jj * (16 * ROWB) + ks * 32);
            #pragma unroll
            for (int i = 0; i < 2; i++)
                #pragma unroll
                for (int jj = 0; jj < 4; jj++) {
                    mma16816(acc[i][2 * jj],     a[i], b[jj][0], b[jj][2]);
                    mma16816(acc[i][2 * jj + 1], a[i], b[jj][1], b[jj][3]);
                }
        }
    }

    // ---------------- epilogue ----------------
    const float2* bp = (const float2*)(bias + n0 + wn * 64);
    float2 bv[8];
    #pragma unroll
    for (int j = 0; j < 8; j++) bv[j] = bp[j * 4 + (lane & 3)];

    #pragma unroll
    for (int i = 0; i < 2; i++) {
        int m_lo = m0 + wm * 32 + i * 16 + (lane >> 2);
        #pragma unroll
        for (int j = 0; j < 8; j++) {
            int n = n0 + wn * 64 + j * 8 + (lane & 3) * 2;
            float v0 = acc[i][j][0] + bv[j].x;
            float v1 = acc[i][j][1] + bv[j].y;
            float v2 = acc[i][j][2] + bv[j].x;
            float v3 = acc[i][j][3] + bv[j].y;
            if (relu) {
                v0 = fmaxf(v0, 0.f); v1 = fmaxf(v1, 0.f);
                v2 = fmaxf(v2, 0.f); v3 = fmaxf(v3, 0.f);
            }
            if (Cf) {
                *(float2*)(Cf + (size_t)m_lo * CmS + n)        = make_float2(v0, v1);
                *(float2*)(Cf + (size_t)(m_lo + 8) * CmS + n)  = make_float2(v2, v3);
            }
            if (Chi) {
                __half2 ph = __halves2half2(__float2half_rn(v0), __float2half_rn(v1));
                *(uint32_t*)(Chi + (size_t)m_lo * CmS + n) = *(uint32_t*)&ph;
                ph = __halves2half2(__float2half_rn(v2), __float2half_rn(v3));
                *(uint32_t*)(Chi + (size_t)(m_lo + 8) * CmS + n) = *(uint32_t*)&ph;
            }
        }
    }
}

// ---------------- weight transpose + fp16 convert (layer-batched) --------
__global__ void wconvL_kernel(const float* __restrict__ src,
                              __half* __restrict__ dh,
                              int K, int N, int dstLd,
                              size_t srcLS, size_t dstLS) {
    __shared__ float ts[32][33];
    int L = blockIdx.z;
    src += L * srcLS; dh += L * dstLS;
    int n0 = blockIdx.x * 32, k0 = blockIdx.y * 32;
    int tx = threadIdx.x, ty = threadIdx.y;
    #pragma unroll
    for (int j = 0; j < 4; j++)
        ts[ty + 8 * j][tx] = src[(size_t)(k0 + ty + 8 * j) * N + n0 + tx];
    __syncthreads();
    #pragma unroll
    for (int j = 0; j < 4; j++) {
        float v = ts[tx][ty + 8 * j];
        size_t di = (size_t)(n0 + ty + 8 * j) * dstLd + k0 + tx;
        dh[di] = __float2half_rn(v);
    }
}

// all QKV conversions in one launch: z = layer*3 + mat
__global__ void wconv3_kernel(const float* __restrict__ srcQ,
                              const float* __restrict__ srcK,
                              const float* __restrict__ srcV,
                              __half* __restrict__ dh) {
    __shared__ float ts[32][33];
    int z = blockIdx.z;
    int L = z / 3, mat = z % 3;
    const float* src = (mat == 0) ? srcQ : (mat == 1) ? srcK : srcV;
    src += (size_t)L * CD * CHDK;
    dh  += (size_t)L * CQKV * CD;
    int rowOff = mat * CHDK;
    int n0 = blockIdx.x * 32, k0 = blockIdx.y * 32;
    int tx = threadIdx.x, ty = threadIdx.y;
    #pragma unroll
    for (int j = 0; j < 4; j++)
        ts[ty + 8 * j][tx] = src[(size_t)(k0 + ty + 8 * j) * CHDK + n0 + tx];
    __syncthreads();
    #pragma unroll
    for (int j = 0; j < 4; j++) {
        float v = ts[tx][ty + 8 * j];
        size_t di = (size_t)(rowOff + n0 + ty + 8 * j) * CD + k0 + tx;
        dh[di] = __float2half_rn(v);
    }
}

__global__ void wconv_ea_kernel(const float* __restrict__ src) {
    __shared__ float ts[32][33];
    int n0 = blockIdx.x * 32, k0 = blockIdx.y * 32;
    int tx = threadIdx.x, ty = threadIdx.y;
    #pragma unroll
    for (int j = 0; j < 4; j++) {
        int n = n0 + tx;
        ts[ty + 8 * j][tx] = (n < 770) ? src[(size_t)(k0 + ty + 8 * j) * 770 + n] : 0.f;
    }
    __syncthreads();
    #pragma unroll
    for (int j = 0; j < 4; j++) {
        int n = n0 + ty + 8 * j;
        if (n < 770)
            g_weah[(size_t)n * CD + k0 + tx] = __float2half_rn(ts[tx][ty + 8 * j]);
    }
}

__global__ void bqkv_kernel(const float* __restrict__ bq,
                            const float* __restrict__ bk,
                            const float* __restrict__ bv,
                            const float* __restrict__ b_ea) {
    int i = blockIdx.x;
    for (int j = threadIdx.x; j < CQKV; j += 256)
        g_bqkv[i * CQKV + j] =
            (j < CHDK) ? bq[i * CHDK + j] :
            (j < 2 * CHDK) ? bk[i * CHDK + j - CHDK] : bv[i * CHDK + j - 2 * CHDK];
    if (i == 0)
        for (int j = threadIdx.x; j < CEAP; j += 256)
            g_bea[j] = (j < 770) ? b_ea[j] : 0.f;
}

// ---------------- gather spans into g_x (+ fp16) ----------------
__global__ void gather_kernel(const float* __restrict__ q_enc,
                              const int* __restrict__ ranges) {
    int row = blockIdx.x;
    int be = row >> 4, l = row & 15;
    int b = be >> 5, e = be & 31;
    int st = ranges[(b * CE + e) * 2];
    int en = ranges[(b * CE + e) * 2 + 1];
    int src = min(max(st + l, 0), CS - 1);
    bool m = l < (en - st);
    const float* s = q_enc + ((size_t)b * CS + src) * CD;
    size_t base = (size_t)row * CD;
    for (int i = threadIdx.x; i < CD; i += 256) {
        float v = m ? s[i] : 0.f;
        g_x[base + i] = v;
        g_xh[base + i] = __float2half_rn(v);
    }
}

// ---------------- per-(span,head) attention ----------------
__global__ void attn_kernel() {
    int nh = blockIdx.x;
    int n = nh / CH, h = nh % CH;
    __shared__ float qs[16][129], ks[16][129], vs[16][129];
    __shared__ float sc[16][17];
    int tid = threadIdx.x;
    for (int idx = tid; idx < 16 * 128; idx += 128) {
        int l = idx >> 7, d = idx & 127;
        size_t base = ((size_t)(n * CL + l)) * CQKV + h * CDK + d;
        qs[l][d] = __half2float(g_qkvh[base]);
        ks[l][d] = __half2float(g_qkvh[base + CHDK]);
        vs[l][d] = __half2float(g_qkvh[base + 2 * CHDK]);
    }
    __syncthreads();
    const float scale = 0.088388347648318447f;
    for (int p = tid; p < 256; p += 128) {
        int qi = p >> 4, ki = p & 15;
        float s = 0.f;
        #pragma unroll
        for (int d = 0; d < 128; d++) s += qs[qi][d] * ks[ki][d];
        sc[qi][ki] = s * scale;
    }
    __syncthreads();
    if (tid < 16) {
        float m = -1e30f;
        #pragma unroll
        for (int k = 0; k < 16; k++) m = fmaxf(m, sc[tid][k]);
        float sum = 0.f;
        #pragma unroll
        for (int k = 0; k < 16; k++) { float e = __expf(sc[tid][k] - m); sc[tid][k] = e; sum += e; }
        float inv = 1.f / sum;
        #pragma unroll
        for (int k = 0; k < 16; k++) sc[tid][k] *= inv;
    }
    __syncthreads();
    int d = tid;
    #pragma unroll
    for (int qi = 0; qi < 16; qi++) {
        float acc = 0.f;
        #pragma unroll
        for (int k = 0; k < 16; k++) acc += sc[qi][k] * vs[k][d];
        g_oh[((size_t)(n * CL + qi)) * CHDK + h * CDK + d] = __float2half_rn(acc);
    }
}

__global__ void attn0_kernel() {
    int nh = blockIdx.x;
    int n = nh / CH, h = nh % CH;
    __shared__ float ks[16][129], vs[16][129];
    __shared__ float q0[128];
    __shared__ float p[16];
    int tid = threadIdx.x;
    for (int idx = tid; idx < 16 * 128; idx += 128) {
        int l = idx >> 7, d = idx & 127;
        size_t base = ((size_t)(n * CL + l)) * CQKV + h * CDK + d;
        ks[l][d] = __half2float(g_qkvh[base + CHDK]);
        vs[l][d] = __half2float(g_qkvh[base + 2 * CHDK]);
    }
    q0[tid] = __half2float(g_qkvh[((size_t)(n * CL)) * CQKV + h * CDK + tid]);
    __syncthreads();
    const float scale = 0.088388347648318447f;
    if (tid < 16) {
        float s = 0.f;
        #pragma unroll
        for (int d = 0; d < 128; d++) s += q0[d] * ks[tid][d];
        p[tid] = s * scale;
    }
    __syncthreads();
    if (tid == 0) {
        float m = -1e30f;
        #pragma unroll
        for (int k = 0; k < 16; k++) m = fmaxf(m, p[k]);
        float sum = 0.f;
        #pragma unroll
        for (int k = 0; k < 16; k++) { float e = __expf(p[k] - m); p[k] = e; sum += e; }
        float inv = 1.f / sum;
        #pragma unroll
        for (int k = 0; k < 16; k++) p[k] *= inv;
    }
    __syncthreads();
    float acc = 0.f;
    #pragma unroll
    for (int k = 0; k < 16; k++) acc += p[k] * vs[k][tid];
    g_oh[(size_t)n * CHDK + h * CDK + tid] = __float2half_rn(acc);
}

// ---------------- LayerNorm kernels ----------------
__device__ __forceinline__ float blockReduceSum(float val) {
    __shared__ float sh[32];
    int lane = threadIdx.x & 31, wid = threadIdx.x >> 5;
    #pragma unroll
    for (int o = 16; o > 0; o >>= 1) val += __shfl_xor_sync(0xffffffffu, val, o);
    if (lane == 0) sh[wid] = val;
    __syncthreads();
    int nw = (blockDim.x + 31) >> 5;
    val = (threadIdx.x < nw) ? sh[lane] : 0.f;
    if (wid == 0) {
        #pragma unroll
        for (int o = 16; o > 0; o >>= 1) val += __shfl_xor_sync(0xffffffffu, val, o);
    }
    return val;
}

__global__ void add_ln_kernel(const float* __restrict__ gamma,
                              const float* __restrict__ beta) {
    int row = blockIdx.x;
    int tid = threadIdx.x;
    float v[3];
    float s = 0.f;
    #pragma unroll
    for (int j = 0; j < 3; j++) {
        size_t idx = (size_t)row * CD + tid + j * 256;
        v[j] = g_x[idx] + g_t[idx];
        s += v[j];
    }
    s = blockReduceSum(s);
    __shared__ float mean_s, rstd_s;
    if (tid == 0) mean_s = s * (1.f / CD);
    __syncthreads();
    float m = mean_s;
    float vv = 0.f;
    #pragma unroll
    for (int j = 0; j < 3; j++) { float d = v[j] - m; vv += d * d; }
    vv = blockReduceSum(vv);
    if (tid == 0) rstd_s = rsqrtf(vv * (1.f / CD) + 1e-5f);
    __syncthreads();
    float r = rstd_s;
    #pragma unroll
    for (int j = 0; j < 3; j++) {
        int c = tid + j * 256;
        float o = (v[j] - m) * r * gamma[c] + beta[c];
        size_t idx = (size_t)row * CD + c;
        g_x[idx] = o;
        g_xh[idx] = __float2half_rn(o);
    }
}

__global__ void ln1_last_kernel(const float* __restrict__ gamma,
                                const float* __restrict__ beta) {
    int r = blockIdx.x;
    int tid = threadIdx.x;
    float v[3];
    float s = 0.f;
    #pragma unroll
    for (int j = 0; j < 3; j++) {
        int c = tid + j * 256;
        v[j] = g_x[((size_t)r * CL) * CD + c] + g_t[(size_t)r * CD + c];
        s += v[j];
    }
    s = blockReduceSum(s);
    __shared__ float mean_s, rstd_s;
    if (tid == 0) mean_s = s * (1.f / CD);
    __syncthreads();
    float m = mean_s;
    float vv = 0.f;
    #pragma unroll
    for (int j = 0; j < 3; j++) { float d = v[j] - m; vv += d * d; }
    vv = blockReduceSum(vv);
    if (tid == 0) rstd_s = rsqrtf(vv * (1.f / CD) + 1e-5f);
    __syncthreads();
    float rr = rstd_s;
    #pragma unroll
    for (int j = 0; j < 3; j++) {
        int c = tid + j * 256;
        float o = (v[j] - m) * rr * gamma[c] + beta[c];
        size_t idx = (size_t)r * CD + c;
        g_xc[idx] = o;
        g_xch[idx] = __float2half_rn(o);
    }
}

__global__ void ln2_last_kernel(const float* __restrict__ gamma,
                                const float* __restrict__ beta) {
    int r = blockIdx.x;
    int tid = threadIdx.x;
    float v[3];
    float s = 0.f;
    #pragma unroll
    for (int j = 0; j < 3; j++) {
        size_t idx = (size_t)r * CD + tid + j * 256;
        v[j] = g_xc[idx] + g_t[idx];
        s += v[j];
    }
    s = blockReduceSum(s);
    __shared__ float mean_s, rstd_s;
    if (tid == 0) mean_s = s * (1.f / CD);
    __syncthreads();
    float m = mean_s;
    float vv = 0.f;
    #pragma unroll
    for (int j = 0; j < 3; j++) { float d = v[j] - m; vv += d * d; }
    vv = blockReduceSum(vv);
    if (tid == 0) rstd_s = rsqrtf(vv * (1.f / CD) + 1e-5f);
    __syncthreads();
    float rr = rstd_s;
    #pragma unroll
    for (int j = 0; j < 3; j++) {
        int c = tid + j * 256;
        float o = (v[j] - m) * rr * gamma[c] + beta[c];
        size_t idx = (size_t)r * CD + c;
        g_ent[idx] = o;
        g_enth[idx] = __float2half_rn(o);
    }
}

// ---------------- tail kernels ----------------
__global__ void pool_attn_kernel(const float* __restrict__ q_enc,
                                 const float* __restrict__ hint) {
    int t = blockIdx.x, b = blockIdx.y;
    __shared__ float qv[770];
    __shared__ float lg[32];
    int tid = threadIdx.x;
    for (int i = tid; i < 770; i += 256)
        qv[i] = (i < CD) ? q_enc[((size_t)b * CS + t) * CD + i]
                         : hint[((size_t)b * CTQ + t) * 2 + (i - CD)];
    __syncthreads();
    int e = tid >> 3, sub = tid & 7;
    const float* ep = g_entp + ((size_t)b * CE + e) * CEAP;
    float p = 0.f;
    for (int d = sub; d < 770; d += 8) p += qv[d] * ep[d];
    p += __shfl_down_sync(0xffffffffu, p, 4, 8);
    p += __shfl_down_sync(0xffffffffu, p, 2, 8);
    p += __shfl_down_sync(0xffffffffu, p, 1, 8);
    if (sub == 0) lg[e] = p;
    __syncthreads();
    if (tid < 32) {
        float v = lg[tid];
        float m = v;
        #pragma unroll
        for (int o = 16; o > 0; o >>= 1) m = fmaxf(m, __shfl_xor_sync(0xffffffffu, m, o));
        float ex = __expf(v - m);
        float sm = ex;
        #pragma unroll
        for (int o = 16; o > 0; o >>= 1) sm += __shfl_xor_sync(0xffffffffu, sm, o);
        g_attnw[((size_t)b * CTQ + t) * CE + tid] = ex / sm;
    }
}

__global__ void pool_wa_kernel(const int* __restrict__ qlen) {
    int b = blockIdx.x;
    int tid = threadIdx.x;
    __shared__ float A[32];
    int n = qlen[b];
    if (tid < 32) {
        float s = 0.f;
        for (int t = 0; t < n; t++) s += g_attnw[((size_t)b * CTQ + t) * CE + tid];
        A[tid] = s;
    }
    __syncthreads();
    #pragma unroll
    for (int j = 0; j < 3; j++) {
        int d = tid + j * 256;
        float s = 0.f;
        #pragma unroll
        for (int e = 0; e < 32; e++) s += A[e] * g_ent[((size_t)b * CE + e) * CD + d];
        g_wa[(size_t)b * CD + d] = s;
    }
}

// feat (fp16) = [q_enc[b,0,:], wa[b,:]]
__global__ void feat_kernel(const float* __restrict__ q_enc) {
    int b = blockIdx.x;
    for (int i = threadIdx.x; i < 2 * CD; i += 256)
        g_feath[(size_t)b * 2 * CD + i] = __float2half_rn(
            (i < CD) ? q_enc[(size_t)b * CS * CD + i] : g_wa[(size_t)b * CD + (i - CD)]);
}

__global__ void head_out_kernel(const float* __restrict__ W2,
                                const float* __restrict__ b2,
                                float* __restrict__ out) {
    int b = blockIdx.x, tid = threadIdx.x;
    float s = 0.f;
    for (int n = tid; n < CNH; n += 256) s += g_h[(size_t)b * CNH + n] * W2[n];
    s = blockReduceSum(s);
    if (tid == 0) out[b] = s + b2[0];
}

// ---------------- host ----------------
template <typename T>
static T* dsym(const void* symbol) {
    void* p = nullptr;
    cudaGetSymbolAddress(&p, symbol);
    return (T*)p;
}

extern "C" void kernel_launch(void* const* d_in, const int* in_sizes, int n_in,
                              void* d_out, int out_size) {
    const float* q_enc  = (const float*)d_in[0];
    const int*   q_qlen = (const int*)  d_in[1];
    const float* hint   = (const float*)d_in[2];
    const int*   ranges = (const int*)  d_in[3];
    const float* Wq  = (const float*)d_in[4];
    const float* bq  = (const float*)d_in[5];
    const float* Wk  = (const float*)d_in[6];
    const float* bk  = (const float*)d_in[7];
    const float* Wv  = (const float*)d_in[8];
    const float* bv  = (const float*)d_in[9];
    const float* Wo  = (const float*)d_in[10];
    const float* bo  = (const float*)d_in[11];
    const float* ln1g = (const float*)d_in[12];
    const float* ln1b = (const float*)d_in[13];
    const float* Wf1 = (const float*)d_in[14];
    const float* bf1 = (const float*)d_in[15];
    const float* Wf2 = (const float*)d_in[16];
    const float* bf2 = (const float*)d_in[17];
    const float* ln2g = (const float*)d_in[18];
    const float* ln2b = (const float*)d_in[19];
    const float* W_ea = (const float*)d_in[20];
    const float* b_ea = (const float*)d_in[21];
    const float* W1  = (const float*)d_in[22];
    const float* b1  = (const float*)d_in[23];
    const float* W2  = (const float*)d_in[24];
    const float* b2  = (const float*)d_in[25];
    float* out = (float*)d_out;

    cudaFuncSetAttribute(gemm_mma, cudaFuncAttributeMaxDynamicSharedMemorySize, SMEM_DYN);

    __half* xh  = dsym<__half>(g_xh);
    __half* oh  = dsym<__half>(g_oh);
    __half* fh  = dsym<__half>(g_fh);
    __half* xch = dsym<__half>(g_xch);
    __half* qkvh = dsym<__half>(g_qkvh);
    float* t_  = dsym<float>(g_t);
    __half* wqkvh = dsym<__half>(g_wqkvh);
    __half* woh   = dsym<__half>(g_woh);
    __half* wf1h  = dsym<__half>(g_wf1h);
    __half* wf2h  = dsym<__half>(g_wf2h);
    __half* weah  = dsym<__half>(g_weah);
    __half* enth  = dsym<__half>(g_enth);
    __half* feath = dsym<__half>(g_feath);
    __half* w1h   = dsym<__half>(g_w1h);
    float* bqkv = dsym<float>(g_bqkv);
    float* bea  = dsym<float>(g_bea);
    float* entp = dsym<float>(g_entp);
    float* h_   = dsym<float>(g_h);

    dim3 wblk(32, 8);

    // all QKV weight conversions (3 layers x 3 mats), bias concat, gather
    wconv3_kernel<<<dim3(CHDK/32, CD/32, 3*CNL), wblk>>>(Wq, Wk, Wv, wqkvh);
    bqkv_kernel<<<CNL, 256>>>(bq, bk, bv, b_ea);
    gather_kernel<<<NROWS, 256>>>(q_enc, ranges);

    // layer-0 QKV GEMM
    gemm_mma<<<dim3(CQKV/128, NROWS/64), 128, SMEM_DYN>>>(
        xh, wqkvh, bqkv, nullptr, qkvh, CD, CD, CQKV, 0);

    // remaining weight conversions (layer-batched)
    wconvL_kernel<<<dim3(CD/32, CHDK/32, CNL), wblk>>>(
        Wo, woh, CHDK, CD, CHDK, (size_t)CHDK*CD, (size_t)CD*CHDK);
    wconvL_kernel<<<dim3(CDFF/32, CD/32, CNL), wblk>>>(
        Wf1, wf1h, CD, CDFF, CD, (size_t)CD*CDFF, (size_t)CDFF*CD);
    wconvL_kernel<<<dim3(CD/32, CDFF/32, CNL), wblk>>>(
        Wf2, wf2h, CDFF, CD, CDFF, (size_t)CDFF*CD, (size_t)CD*CDFF);
    wconv_ea_kernel<<<dim3((770 + 31)/32, CD/32), wblk>>>(W_ea);
    wconvL_kernel<<<dim3(CNH/32, (2*CD)/32, 1), wblk>>>(
        W1, w1h, 2*CD, CNH, 2*CD, 0, 0);

    // ---- layers 0 .. NL-2: full-width pipeline ----
    for (int i = 0; i < CNL - 1; i++) {
        size_t oQ  = (size_t)i * CQKV * CD;
        size_t oO  = (size_t)i * CD * CHDK;
        size_t oF1 = (size_t)i * CDFF * CD;
        size_t oF2 = (size_t)i * CD * CDFF;

        if (i > 0) {
            gemm_mma<<<dim3(CQKV/128, NROWS/64), 128, SMEM_DYN>>>(
                xh, wqkvh + oQ, bqkv + i*CQKV, nullptr, qkvh, CD, CD, CQKV, 0);
        }

        attn_kernel<<<NENT * CH, 128>>>();

        gemm_mma<<<dim3(CD/128, NROWS/64), 128, SMEM_DYN>>>(
            oh, woh + oO, bo + i*CD, t_, nullptr, CHDK, CHDK, CD, 0);

        add_ln_kernel<<<NROWS, 256>>>(ln1g + i*CD, ln1b + i*CD);

        gemm_mma<<<dim3(CDFF/128, NROWS/64), 128, SMEM_DYN>>>(
            xh, wf1h + oF1, bf1 + i*CDFF, nullptr, fh, CD, CD, CDFF, 1);

        gemm_mma<<<dim3(CD/128, NROWS/64), 128, SMEM_DYN>>>(
            fh, wf2h + oF2, bf2 + i*CD, t_, nullptr, CDFF, CDFF, CD, 0);

        add_ln_kernel<<<NROWS, 256>>>(ln2g + i*CD, ln2b + i*CD);
    }

    // ---- layer NL-1 (last): only span-row 0 needed post-attention ----
    {
        const int i = CNL - 1;
        size_t oQ  = (size_t)i * CQKV * CD;
        size_t oO  = (size_t)i * CD * CHDK;
        size_t oF1 = (size_t)i * CDFF * CD;
        size_t oF2 = (size_t)i * CD * CDFF;

        // K/V for ALL rows (N = 768, columns CHDK..CQKV)
        gemm_mma<<<dim3((2*CHDK)/128, NROWS/64), 128, SMEM_DYN>>>(
            xh, wqkvh + oQ + (size_t)CHDK*CD, bqkv + i*CQKV + CHDK,
            nullptr, qkvh + CHDK, CD, CD, CQKV, 0);

        // Q only for span-row 0 (compact M = 2048, strided A rows & C rows)
        gemm_mma<<<dim3(CHDK/128, NENT/64), 128, SMEM_DYN>>>(
            xh, wqkvh + oQ, bqkv + i*CQKV,
            nullptr, qkvh, CD, CL*CD, CL*CQKV, 0);

        attn0_kernel<<<NENT * CH, 128>>>();

        gemm_mma<<<dim3(CD/128, NENT/64), 128, SMEM_DYN>>>(
            oh, woh + oO, bo + i*CD, t_, nullptr, CHDK, CHDK, CD, 0);

        ln1_last_kernel<<<NENT, 256>>>(ln1g + i*CD, ln1b + i*CD);

        gemm_mma<<<dim3(CDFF/128, NENT/64), 128, SMEM_DYN>>>(
            xch, wf1h + oF1, bf1 + i*CDFF, nullptr, fh, CD, CD, CDFF, 1);

        gemm_mma<<<dim3(CD/128, NENT/64), 128, SMEM_DYN>>>(
            fh, wf2h + oF2, bf2 + i*CD, t_, nullptr, CDFF, CDFF, CD, 0);

        ln2_last_kernel<<<NENT, 256>>>(ln2g + i*CD, ln2b + i*CD);
    }

    // ---- tail: ent_proj + pooling + head (tensorized) ----
    gemm_mma<<<dim3(CEAP/128, NENT/64), 128, SMEM_DYN>>>(
        enth, weah, bea, entp, nullptr, CD, CD, CEAP, 0);

    pool_attn_kernel<<<dim3(CTQ, CB), 256>>>(q_enc, hint);
    pool_wa_kernel<<<CB, 256>>>(q_qlen);
    feat_kernel<<<CB, 256>>>(q_enc);

    gemm_mma<<<dim3(CNH/128, CB/64), 128, SMEM_DYN>>>(
        feath, w1h, b1, h_, nullptr, 2*CD, 2*CD, CNH, 1);

    head_out_kernel<<<CB, 256>>>(W2, b2, out);
}